// round 7
// baseline (speedup 1.0000x reference)
#include <cuda_runtime.h>
#include <cuda_bf16.h>
#include <math.h>

#define NB 64
#define NP 24564
#define NM 16
#define NC 21
#define TPB 256
#define NBLK ((NP + TPB - 1) / TPB)   // 96

// ---------------- device scratch ----------------
__device__ unsigned long long g_winner[NB * NM];   // packed (iou_bits<<32)|(~prior)
__device__ float              g_mined[NB * NP];    // mined conf loss (0 at positives)
__device__ int                g_num_pos[NB];
__device__ double             g_loss_l;
__device__ double             g_loss_c;

// ---------- shared exact-math helpers (bit-identical across kernels) ----------
__device__ __forceinline__ void prior_corners(float4 pr, float& x1, float& y1,
                                              float& x2, float& y2, float& pa) {
    float hz = __fmul_rn(pr.z, 0.5f), hw = __fmul_rn(pr.w, 0.5f);
    x1 = __fsub_rn(pr.x, hz); y1 = __fsub_rn(pr.y, hw);
    x2 = __fadd_rn(pr.x, hz); y2 = __fadd_rn(pr.y, hw);
    pa = __fmul_rn(__fsub_rn(x2, x1), __fsub_rn(y2, y1));
}

__device__ __forceinline__ float iou_exact(float px1, float py1, float px2, float py2,
                                           float pa, float tx1, float ty1, float tx2,
                                           float ty2, float ta) {
    float ix = fmaxf(__fsub_rn(fminf(px2, tx2), fmaxf(px1, tx1)), 0.0f);
    float iy = fmaxf(__fsub_rn(fminf(py2, ty2), fmaxf(py1, ty1)), 0.0f);
    float inter = __fmul_rn(ix, iy);
    float uni = __fsub_rn(__fadd_rn(pa, ta), inter);
    return __fdiv_rn(inter, uni);
}

__device__ __forceinline__ float sl1e(float d) {
    float a = fabsf(d);
    return (a < 1.0f) ? __fmul_rn(0.5f, __fmul_rn(d, d)) : __fsub_rn(a, 0.5f);
}

// smooth-L1 loc loss of prior p against truth box (explicit rounding; logf deterministic)
__device__ __forceinline__ float loc_loss(const float4 lp, const float4 pr,
                                          float tx1, float ty1, float tx2, float ty2) {
    float gx = __fdiv_rn(__fsub_rn(__fmul_rn(__fadd_rn(tx1, tx2), 0.5f), pr.x),
                         __fmul_rn(0.1f, pr.z));
    float gy = __fdiv_rn(__fsub_rn(__fmul_rn(__fadd_rn(ty1, ty2), 0.5f), pr.y),
                         __fmul_rn(0.1f, pr.w));
    float gw = __fdiv_rn(logf(__fdiv_rn(__fsub_rn(tx2, tx1), pr.z)), 0.2f);
    float gh = __fdiv_rn(logf(__fdiv_rn(__fsub_rn(ty2, ty1), pr.w)), 0.2f);
    return __fadd_rn(__fadd_rn(sl1e(__fsub_rn(lp.x, gx)), sl1e(__fsub_rn(lp.y, gy))),
                     __fadd_rn(sl1e(__fsub_rn(lp.z, gw)), sl1e(__fsub_rn(lp.w, gh))));
}

// LSE with fixed op order (must match between k_fused and k_force)
__device__ __forceinline__ float lse21(const float* v) {
    float mx = v[0];
#pragma unroll
    for (int c = 1; c < NC; c++) mx = fmaxf(mx, v[c]);
    float s = 0.0f;
#pragma unroll
    for (int c = 0; c < NC; c++) s = __fadd_rn(s, __expf(__fsub_rn(v[c], mx)));
    return __fadd_rn(mx, __logf(s));
}

// ---------------- kernel A: init ----------------
__global__ void k_init() {
    int i = blockIdx.x * blockDim.x + threadIdx.x;
    if (i < NB * NM) g_winner[i] = 0ull;
    if (i < NB) g_num_pos[i] = 0;
    if (i == 0) { g_loss_l = 0.0; g_loss_c = 0.0; }
}

// ---------------- kernel B: FUSED match + LSE + losses ----------------
__global__ void k_fused(const float* __restrict__ loc,
                        const float* __restrict__ conf,
                        const float* __restrict__ priors,
                        const float* __restrict__ targets) {
    const int n   = blockIdx.y;
    const int tid = threadIdx.x;
    const int rb  = blockIdx.x * TPB;
    const int lane = tid & 31;

    __shared__ float t_x1[NM], t_y1[NM], t_x2[NM], t_y2[NM], t_area[NM], t_lab[NM];
    __shared__ unsigned long long sh_key[NM];
    __shared__ float sbuf[TPB * NC];
    __shared__ float s_ll, s_plc; __shared__ int s_np;

    if (tid < NM) {
        const float* tp = targets + (size_t)(n * NM + tid) * 5;
        float x1 = tp[0], y1 = tp[1], x2 = tp[2], y2 = tp[3];
        t_x1[tid] = x1; t_y1[tid] = y1; t_x2[tid] = x2; t_y2[tid] = y2;
        t_area[tid] = __fmul_rn(__fsub_rn(x2, x1), __fsub_rn(y2, y1));
        t_lab[tid] = tp[4];
        sh_key[tid] = 0ull;
    }
    if (tid == 0) { s_ll = 0.0f; s_plc = 0.0f; s_np = 0; }

    // stage conf rows [rb, rb+rows): coalesced float4 (alignment: (n*NP+rb)%4==0)
    const int rows = min(TPB, NP - rb);
    const int nf4  = rows * NC / 4;   // rows*21 % 4 == 0 for rows in {256,244}
    const float4* src = (const float4*)(conf + ((size_t)n * NP + rb) * NC);
    float4* dst = (float4*)sbuf;
    for (int i = tid; i < nf4; i += TPB) dst[i] = src[i];
    __syncthreads();

    const int p = rb + tid;
    const bool valid = tid < rows;

    // ---- match phase ----
    float px1 = 0.f, py1 = 0.f, px2 = 0.f, py2 = 0.f, pa = 1.f;
    if (valid) {
        float4 pr = ((const float4*)priors)[p];
        prior_corners(pr, px1, py1, px2, py2, pa);
    }
    float best_ov = -1.0f; int best_t = 0;
#pragma unroll
    for (int t = 0; t < NM; t++) {
        float iou = 0.0f;
        if (valid) {
            iou = iou_exact(px1, py1, px2, py2, pa,
                            t_x1[t], t_y1[t], t_x2[t], t_y2[t], t_area[t]);
            if (iou > best_ov) { best_ov = iou; best_t = t; }   // first-index tiebreak
        }
        unsigned b    = __float_as_uint(iou);
        unsigned wmax = __reduce_max_sync(0xFFFFFFFFu, b);
        unsigned ball = __ballot_sync(0xFFFFFFFFu, b == wmax);
        if (valid && lane == (__ffs(ball) - 1)) {
            atomicMax(&sh_key[t],
                      ((unsigned long long)wmax << 32) |
                      (unsigned long long)(0xFFFFFFFFu - (unsigned)p));
        }
    }

    // ---- loss phase (pre-force; k_force applies corrections) ----
    float local_ll = 0.0f, local_plc = 0.0f;
    int   local_np = 0;
    if (valid) {
        int conf_t = (best_ov < 0.5f) ? 0 : ((int)t_lab[best_t] + 1);
        bool pos = conf_t > 0;

        const float* v = sbuf + tid * NC;
        float lse = lse21(v);
        float lc  = __fsub_rn(lse, v[conf_t]);

        g_mined[(size_t)n * NP + p] = pos ? 0.0f : lc;

        if (pos) {
            local_np  = 1;
            local_plc = lc;
            float4 pr = ((const float4*)priors)[p];
            float4 lp = ((const float4*)loc)[(size_t)n * NP + p];
            local_ll = loc_loss(lp, pr, t_x1[best_t], t_y1[best_t],
                                t_x2[best_t], t_y2[best_t]);
        }
    }

#pragma unroll
    for (int o = 16; o; o >>= 1) {
        local_ll  += __shfl_down_sync(0xFFFFFFFFu, local_ll,  o);
        local_plc += __shfl_down_sync(0xFFFFFFFFu, local_plc, o);
        local_np  += __shfl_down_sync(0xFFFFFFFFu, local_np,  o);
    }
    __syncthreads();
    if (lane == 0) {
        if (local_ll  != 0.0f) atomicAdd(&s_ll,  local_ll);
        if (local_plc != 0.0f) atomicAdd(&s_plc, local_plc);
        if (local_np)          atomicAdd(&s_np,  local_np);
    }
    __syncthreads();
    if (tid < NM && sh_key[tid])
        atomicMax(&g_winner[n * NM + tid], sh_key[tid]);
    if (tid == 0) {
        if (s_np)          atomicAdd(&g_num_pos[n], s_np);
        if (s_ll  != 0.0f) atomicAdd(&g_loss_l, (double)s_ll);
        if (s_plc != 0.0f) atomicAdd(&g_loss_c, (double)s_plc);
    }
}

// ---------------- kernel C: forced-match corrections ----------------
// warp per batch, lane t (<16) per truth. Last-write-wins resolved via match_any.
__global__ void k_force(const float* __restrict__ loc,
                        const float* __restrict__ conf,
                        const float* __restrict__ priors,
                        const float* __restrict__ targets) {
    const int tid  = threadIdx.x;
    const int lane = tid & 31;
    const int warp = tid >> 5;
    const int n    = blockIdx.x * 32 + warp;

    __shared__ float w_x1[32][NM], w_y1[32][NM], w_x2[32][NM], w_y2[32][NM],
                     w_ar[32][NM], w_lb[32][NM];

    if (n < NB && lane < NM) {
        const float* tp = targets + (size_t)(n * NM + lane) * 5;
        float x1 = tp[0], y1 = tp[1], x2 = tp[2], y2 = tp[3];
        w_x1[warp][lane] = x1; w_y1[warp][lane] = y1;
        w_x2[warp][lane] = x2; w_y2[warp][lane] = y2;
        w_ar[warp][lane] = __fmul_rn(__fsub_rn(x2, x1), __fsub_rn(y2, y1));
        w_lb[warp][lane] = tp[4];
    }
    __syncwarp();

    float dll = 0.0f, dlc = 0.0f;
    int   dnp = 0;

    if (n < NB && lane < NM) {
        unsigned long long w = g_winner[n * NM + lane];
        unsigned p = 0xFFFFFFFFu - (unsigned)(w & 0xFFFFFFFFull);

        unsigned peers   = __match_any_sync(0x0000FFFFu, p);
        bool firstOcc = (lane == (__ffs(peers) - 1));
        bool isLast   = (lane == (31 - __clz(peers)));   // last truth wins

        float4 pr = ((const float4*)priors)[p];
        float px1, py1, px2, py2, pa;
        prior_corners(pr, px1, py1, px2, py2, pa);

        const float* row = conf + ((size_t)n * NP + p) * NC;
        float v[NC];
#pragma unroll
        for (int c = 0; c < NC; c++) v[c] = row[c];
        float lse = lse21(v);

        if (firstOcc) {
            // recompute old (pre-force) match for prior p, bit-identical to k_fused
            float best_ov = -1.0f; int best_t = 0;
#pragma unroll
            for (int t = 0; t < NM; t++) {
                float iou = iou_exact(px1, py1, px2, py2, pa,
                                      w_x1[warp][t], w_y1[warp][t],
                                      w_x2[warp][t], w_y2[warp][t], w_ar[warp][t]);
                if (iou > best_ov) { best_ov = iou; best_t = t; }
            }
            int conf_t0 = (best_ov < 0.5f) ? 0 : ((int)w_lb[warp][best_t] + 1);
            if (conf_t0 > 0) {
                // subtract old positive contribution
                dlc -= __fsub_rn(lse, v[conf_t0]);
                float4 lp = ((const float4*)loc)[(size_t)n * NP + p];
                dll -= loc_loss(lp, pr, w_x1[warp][best_t], w_y1[warp][best_t],
                                w_x2[warp][best_t], w_y2[warp][best_t]);
            } else {
                dnp += 1;                 // becomes positive
            }
            g_mined[(size_t)n * NP + p] = 0.0f;   // forced priors are positive
        }
        if (isLast) {
            int ct = (int)w_lb[warp][lane] + 1;
            dlc += __fsub_rn(lse, v[ct]);
            float4 lp = ((const float4*)loc)[(size_t)n * NP + p];
            dll += loc_loss(lp, pr, w_x1[warp][lane], w_y1[warp][lane],
                            w_x2[warp][lane], w_y2[warp][lane]);
        }
    }

#pragma unroll
    for (int o = 16; o; o >>= 1) {
        dll += __shfl_down_sync(0xFFFFFFFFu, dll, o);
        dlc += __shfl_down_sync(0xFFFFFFFFu, dlc, o);
        dnp += __shfl_down_sync(0xFFFFFFFFu, dnp, o);
    }
    if (lane == 0 && n < NB) {
        if (dll != 0.0f) atomicAdd(&g_loss_l, (double)dll);
        if (dlc != 0.0f) atomicAdd(&g_loss_c, (double)dlc);
        if (dnp)         atomicAdd(&g_num_pos[n], dnp);
    }
}

// ---------------- kernel D: per-batch top-k sum via 8-bit radix select ----------------
__global__ void k_topk() {
    extern __shared__ unsigned sv[];        // NP uints (loss bits, all >= 0)
    __shared__ int hist[256];
    __shared__ unsigned s_b; __shared__ int s_acc;
    __shared__ int s_ci; __shared__ float s_cs;

    const int n   = blockIdx.x;
    const int tid = threadIdx.x;
    const int nt  = blockDim.x;                          // 1024
    const int NP_PAD = ((NP + 1023) / 1024) * 1024;      // 24576

    const uint4* src = (const uint4*)(g_mined + (size_t)n * NP);   // NP % 4 == 0
    uint4* dstv = (uint4*)sv;
    for (int i = tid; i < NP / 4; i += nt) dstv[i] = src[i];

    const int k = min(3 * g_num_pos[n], NP - 1);
    __syncthreads();
    if (k <= 0) return;

    unsigned prefix = 0;
    int kr = k;
#pragma unroll
    for (int shift = 24; shift >= 0; shift -= 8) {
        if (tid < 256) hist[tid] = 0;
        __syncthreads();
        for (int i = tid; i < NP_PAD; i += nt) {         // uniform trip count
            const bool inb = i < NP;
            unsigned v = inb ? sv[i] : 0u;
            bool m = inb && ((shift == 24) || ((v >> (shift + 8)) == prefix));
            unsigned active = __ballot_sync(0xFFFFFFFFu, m);
            if (m) {
                unsigned bin = (v >> shift) & 255u;
                unsigned peers = __match_any_sync(active, bin);
                if ((tid & 31) == (__ffs(peers) - 1))
                    atomicAdd(&hist[bin], __popc(peers));
            }
        }
        __syncthreads();
        if (tid == 0) {
            int acc = 0; int b = 255;
            for (; b > 0; b--) { if (acc + hist[b] >= kr) break; acc += hist[b]; }
            s_b = (unsigned)b; s_acc = acc;
        }
        __syncthreads();
        prefix = (prefix << 8) | s_b;
        kr -= s_acc;
    }

    const unsigned u = prefix;
    int   cgt = 0;
    float sum = 0.0f;
    for (int i = tid; i < NP; i += nt) {
        unsigned v = sv[i];
        if (v > u) { cgt++; sum += __uint_as_float(v); }
    }
#pragma unroll
    for (int o = 16; o; o >>= 1) {
        cgt += __shfl_down_sync(0xFFFFFFFFu, cgt, o);
        sum += __shfl_down_sync(0xFFFFFFFFu, sum, o);
    }
    if (tid == 0) { s_ci = 0; s_cs = 0.0f; }
    __syncthreads();
    if ((tid & 31) == 0) { atomicAdd(&s_ci, cgt); atomicAdd(&s_cs, sum); }
    __syncthreads();
    if (tid == 0) {
        float S = s_cs + (float)(k - s_ci) * __uint_as_float(u);
        atomicAdd(&g_loss_c, (double)S);
    }
}

// ---------------- kernel E: finalize ----------------
__global__ void k_final(float* out, int out_size) {
    if (threadIdx.x == 0 && blockIdx.x == 0) {
        int ntot = 0;
        for (int i = 0; i < NB; i++) ntot += g_num_pos[i];
        float nf = (float)ntot;
        out[0] = (float)(g_loss_l / (double)nf);
        if (out_size > 1) out[1] = (float)(g_loss_c / (double)nf);
    }
}

// ---------------- launch ----------------
extern "C" void kernel_launch(void* const* d_in, const int* in_sizes, int n_in,
                              void* d_out, int out_size) {
    const float* loc     = (const float*)d_in[0];
    const float* conf    = (const float*)d_in[1];
    const float* priors  = (const float*)d_in[2];
    const float* targets = (const float*)d_in[3];
    float* out = (float*)d_out;

    static bool attr_set = false;
    if (!attr_set) {
        cudaFuncSetAttribute(k_topk, cudaFuncAttributeMaxDynamicSharedMemorySize,
                             NP * (int)sizeof(unsigned));
        attr_set = true;
    }

    dim3 grid(NBLK, NB);

    k_init<<<(NB * NM + 255) / 256, 256>>>();
    k_fused<<<grid, TPB>>>(loc, conf, priors, targets);
    k_force<<<2, 1024>>>(loc, conf, priors, targets);
    k_topk<<<NB, 1024, NP * sizeof(unsigned)>>>();
    k_final<<<1, 32>>>(out, out_size);
}

// round 8
// speedup vs baseline: 1.1196x; 1.1196x over previous
#include <cuda_runtime.h>
#include <cuda_bf16.h>
#include <math.h>

#define NB 64
#define NP 24564
#define NM 16
#define NC 21
#define TPB 256
#define NBLK ((NP + TPB - 1) / TPB)   // 96
#define NHB 4096                      // hist bins (top-12 float bits)
#define GSEG 6                        // gather segments per batch

// ---------------- device scratch ----------------
__device__ unsigned long long g_winner[NB * NM];   // packed (iou_bits<<32)|(~prior)
__device__ float              g_mined[NB * NP];    // mined conf loss (0 at positives)
__device__ unsigned           g_hist[NB * NHB];    // per-batch 12-bit histograms
__device__ float              g_cand[NB * NP];     // threshold-bin candidates
__device__ int                g_cnt[NB];           // candidate counts
__device__ double             g_sumhi[NB];         // sum of values in bins > B
__device__ int                g_selB[NB], g_selkr[NB];
__device__ int                g_num_pos[NB];
__device__ double             g_loss_l;
__device__ double             g_loss_c;

// ---------- shared exact-math helpers (identical in k_fused / k_force) ----------
__device__ __forceinline__ void prior_corners(float4 pr, float& x1, float& y1,
                                              float& x2, float& y2, float& pa) {
    float hz = __fmul_rn(pr.z, 0.5f), hw = __fmul_rn(pr.w, 0.5f);
    x1 = __fsub_rn(pr.x, hz); y1 = __fsub_rn(pr.y, hw);
    x2 = __fadd_rn(pr.x, hz); y2 = __fadd_rn(pr.y, hw);
    pa = __fmul_rn(__fsub_rn(x2, x1), __fsub_rn(y2, y1));
}

__device__ __forceinline__ float iou_fast(float px1, float py1, float px2, float py2,
                                          float pa, float4 tb, float ta) {
    float ix = fmaxf(__fsub_rn(fminf(px2, tb.z), fmaxf(px1, tb.x)), 0.0f);
    float iy = fmaxf(__fsub_rn(fminf(py2, tb.w), fmaxf(py1, tb.y)), 0.0f);
    float inter = __fmul_rn(ix, iy);
    float uni = __fsub_rn(__fadd_rn(pa, ta), inter);
    return __fdividef(inter, uni);
}

__device__ __forceinline__ float sl1e(float d) {
    float a = fabsf(d);
    return (a < 1.0f) ? __fmul_rn(0.5f, __fmul_rn(d, d)) : __fsub_rn(a, 0.5f);
}

__device__ __forceinline__ float loc_loss(const float4 lp, const float4 pr, float4 tb) {
    float gx = __fdividef(__fsub_rn(__fmul_rn(__fadd_rn(tb.x, tb.z), 0.5f), pr.x),
                          __fmul_rn(0.1f, pr.z));
    float gy = __fdividef(__fsub_rn(__fmul_rn(__fadd_rn(tb.y, tb.w), 0.5f), pr.y),
                          __fmul_rn(0.1f, pr.w));
    float gw = __fdividef(__logf(__fdividef(__fsub_rn(tb.z, tb.x), pr.z)), 0.2f);
    float gh = __fdividef(__logf(__fdividef(__fsub_rn(tb.w, tb.y), pr.w)), 0.2f);
    return __fadd_rn(__fadd_rn(sl1e(__fsub_rn(lp.x, gx)), sl1e(__fsub_rn(lp.y, gy))),
                     __fadd_rn(sl1e(__fsub_rn(lp.z, gw)), sl1e(__fsub_rn(lp.w, gh))));
}

__device__ __forceinline__ float lse21(const float* v) {
    float mx = v[0];
#pragma unroll
    for (int c = 1; c < NC; c++) mx = fmaxf(mx, v[c]);
    float s = 0.0f;
#pragma unroll
    for (int c = 0; c < NC; c++) s = __fadd_rn(s, __expf(__fsub_rn(v[c], mx)));
    return __fadd_rn(mx, __logf(s));
}

// ---------------- kernel A: init ----------------
__global__ void k_init() {
    int i = blockIdx.x * blockDim.x + threadIdx.x;
    if (i < NB * NHB) g_hist[i] = 0u;
    if (i < NB * NM) g_winner[i] = 0ull;
    if (i < NB) { g_num_pos[i] = 0; g_cnt[i] = 0; g_sumhi[i] = 0.0; }
    if (i == 0) { g_loss_l = 0.0; g_loss_c = 0.0; }
}

// ---------------- kernel B: FUSED match + LSE + losses + histogram ----------------
__global__ void k_fused(const float* __restrict__ loc,
                        const float* __restrict__ conf,
                        const float* __restrict__ priors,
                        const float* __restrict__ targets) {
    const int n   = blockIdx.y;
    const int tid = threadIdx.x;
    const int rb  = blockIdx.x * TPB;
    const int lane = tid & 31;

    __shared__ float4 t_box[NM];          // {x1,y1,x2,y2}
    __shared__ float  t_area[NM], t_lab[NM];
    __shared__ unsigned long long sh_key[NM];
    __shared__ float sbuf[TPB * NC];
    __shared__ float s_ll, s_plc; __shared__ int s_np;

    if (tid < NM) {
        const float* tp = targets + (size_t)(n * NM + tid) * 5;
        float x1 = tp[0], y1 = tp[1], x2 = tp[2], y2 = tp[3];
        t_box[tid] = make_float4(x1, y1, x2, y2);
        t_area[tid] = __fmul_rn(__fsub_rn(x2, x1), __fsub_rn(y2, y1));
        t_lab[tid] = tp[4];
        sh_key[tid] = 0ull;
    }
    if (tid == 0) { s_ll = 0.0f; s_plc = 0.0f; s_np = 0; }

    const int rows = min(TPB, NP - rb);
    const int nf4  = rows * NC / 4;
    const float4* src = (const float4*)(conf + ((size_t)n * NP + rb) * NC);
    float4* dst = (float4*)sbuf;
    for (int i = tid; i < nf4; i += TPB) dst[i] = src[i];
    __syncthreads();

    const int p = rb + tid;
    const bool valid = tid < rows;

    float px1 = 0.f, py1 = 0.f, px2 = 0.f, py2 = 0.f, pa = 1.f;
    if (valid) {
        float4 pr = ((const float4*)priors)[p];
        prior_corners(pr, px1, py1, px2, py2, pa);
    }
    float best_ov = -1.0f; int best_t = 0;
#pragma unroll
    for (int t = 0; t < NM; t++) {
        float iou = 0.0f;
        if (valid) {
            iou = iou_fast(px1, py1, px2, py2, pa, t_box[t], t_area[t]);
            if (iou > best_ov) { best_ov = iou; best_t = t; }
        }
        unsigned b    = __float_as_uint(iou);
        unsigned wmax = __reduce_max_sync(0xFFFFFFFFu, b);
        if (valid && b == wmax && b != 0u) {      // ties resolved by atomicMax key
            atomicMax(&sh_key[t],
                      ((unsigned long long)wmax << 32) |
                      (unsigned long long)(0xFFFFFFFFu - (unsigned)p));
        }
    }

    float local_ll = 0.0f, local_plc = 0.0f;
    int   local_np = 0;
    float mined = 0.0f;
    if (valid) {
        int conf_t = (best_ov < 0.5f) ? 0 : ((int)t_lab[best_t] + 1);
        bool pos = conf_t > 0;

        const float* v = sbuf + tid * NC;
        float lse = lse21(v);
        float lc  = __fsub_rn(lse, v[conf_t]);

        mined = pos ? 0.0f : lc;
        g_mined[(size_t)n * NP + p] = mined;

        if (pos) {
            local_np  = 1;
            local_plc = lc;
            float4 pr = ((const float4*)priors)[p];
            float4 lp = ((const float4*)loc)[(size_t)n * NP + p];
            local_ll = loc_loss(lp, pr, t_box[best_t]);
        }
    }

    // per-batch 12-bit histogram (warp-aggregated)
    {
        unsigned hv = valid ? (__float_as_uint(mined) >> 20) : 0xFFFFu;
        unsigned peers = __match_any_sync(0xFFFFFFFFu, hv);
        if (hv < NHB && lane == (__ffs(peers) - 1))
            atomicAdd(&g_hist[n * NHB + hv], (unsigned)__popc(peers));
    }

#pragma unroll
    for (int o = 16; o; o >>= 1) {
        local_ll  += __shfl_down_sync(0xFFFFFFFFu, local_ll,  o);
        local_plc += __shfl_down_sync(0xFFFFFFFFu, local_plc, o);
        local_np  += __shfl_down_sync(0xFFFFFFFFu, local_np,  o);
    }
    __syncthreads();
    if (lane == 0) {
        if (local_ll  != 0.0f) atomicAdd(&s_ll,  local_ll);
        if (local_plc != 0.0f) atomicAdd(&s_plc, local_plc);
        if (local_np)          atomicAdd(&s_np,  local_np);
    }
    __syncthreads();
    if (tid < NM && sh_key[tid])
        atomicMax(&g_winner[n * NM + tid], sh_key[tid]);
    if (tid == 0) {
        if (s_np)          atomicAdd(&g_num_pos[n], s_np);
        if (s_ll  != 0.0f) atomicAdd(&g_loss_l, (double)s_ll);
        if (s_plc != 0.0f) atomicAdd(&g_loss_c, (double)s_plc);
    }
}

// ---------------- kernel C: forced-match corrections (+ hist fixups) ----------------
__global__ void k_force(const float* __restrict__ loc,
                        const float* __restrict__ conf,
                        const float* __restrict__ priors,
                        const float* __restrict__ targets) {
    const int tid  = threadIdx.x;
    const int lane = tid & 31;
    const int warp = tid >> 5;
    const int n    = blockIdx.x * 32 + warp;

    __shared__ float4 w_box[32][NM];
    __shared__ float  w_ar[32][NM], w_lb[32][NM];

    if (n < NB && lane < NM) {
        const float* tp = targets + (size_t)(n * NM + lane) * 5;
        float x1 = tp[0], y1 = tp[1], x2 = tp[2], y2 = tp[3];
        w_box[warp][lane] = make_float4(x1, y1, x2, y2);
        w_ar[warp][lane] = __fmul_rn(__fsub_rn(x2, x1), __fsub_rn(y2, y1));
        w_lb[warp][lane] = tp[4];
    }
    __syncwarp();

    float dll = 0.0f, dlc = 0.0f;
    int   dnp = 0;

    if (n < NB && lane < NM) {
        unsigned long long w = g_winner[n * NM + lane];
        unsigned p = 0xFFFFFFFFu - (unsigned)(w & 0xFFFFFFFFull);

        unsigned peers = __match_any_sync(0x0000FFFFu, p);
        bool firstOcc = (lane == (__ffs(peers) - 1));
        bool isLast   = (lane == (31 - __clz(peers)));   // last truth wins

        float4 pr = ((const float4*)priors)[p];
        float px1, py1, px2, py2, pa;
        prior_corners(pr, px1, py1, px2, py2, pa);

        const float* row = conf + ((size_t)n * NP + p) * NC;
        float v[NC];
#pragma unroll
        for (int c = 0; c < NC; c++) v[c] = row[c];
        float lse = lse21(v);

        if (firstOcc) {
            float best_ov = -1.0f; int best_t = 0;
#pragma unroll
            for (int t = 0; t < NM; t++) {
                float iou = iou_fast(px1, py1, px2, py2, pa, w_box[warp][t], w_ar[warp][t]);
                if (iou > best_ov) { best_ov = iou; best_t = t; }
            }
            int conf_t0 = (best_ov < 0.5f) ? 0 : ((int)w_lb[warp][best_t] + 1);
            if (conf_t0 > 0) {
                dlc -= __fsub_rn(lse, v[conf_t0]);
                float4 lp = ((const float4*)loc)[(size_t)n * NP + p];
                dll -= loc_loss(lp, pr, w_box[warp][best_t]);
            } else {
                dnp += 1;
                // hist fixup: value lc_old leaves its bin, a zero enters bin 0
                float lc_old = __fsub_rn(lse, v[0]);
                atomicAdd(&g_hist[n * NHB + (__float_as_uint(lc_old) >> 20)], 0xFFFFFFFFu);
                atomicAdd(&g_hist[n * NHB + 0], 1u);
            }
            g_mined[(size_t)n * NP + p] = 0.0f;
        }
        if (isLast) {
            int ct = (int)w_lb[warp][lane] + 1;
            dlc += __fsub_rn(lse, v[ct]);
            float4 lp = ((const float4*)loc)[(size_t)n * NP + p];
            dll += loc_loss(lp, pr, w_box[warp][lane]);
        }
    }

#pragma unroll
    for (int o = 16; o; o >>= 1) {
        dll += __shfl_down_sync(0xFFFFFFFFu, dll, o);
        dlc += __shfl_down_sync(0xFFFFFFFFu, dlc, o);
        dnp += __shfl_down_sync(0xFFFFFFFFu, dnp, o);
    }
    if (lane == 0 && n < NB) {
        if (dll != 0.0f) atomicAdd(&g_loss_l, (double)dll);
        if (dlc != 0.0f) atomicAdd(&g_loss_c, (double)dlc);
        if (dnp)         atomicAdd(&g_num_pos[n], dnp);
    }
}

// ---------------- kernel D: find threshold bin B + residual kr ----------------
__global__ void k_sel() {        // 64 blocks x 256 threads
    const int n = blockIdx.x, tid = threadIdx.x;
    __shared__ unsigned h[NHB];
    __shared__ int csum[256];

    for (int i = tid; i < NHB; i += 256) h[i] = g_hist[n * NHB + i];
    __syncthreads();

    int c = 0;
#pragma unroll
    for (int j = 0; j < 16; j++) c += (int)h[tid * 16 + j];
    csum[tid] = c;
    __syncthreads();
    for (int off = 1; off < 256; off <<= 1) {          // inclusive suffix scan
        int add = (tid + off < 256) ? csum[tid + off] : 0;
        __syncthreads();
        csum[tid] += add;
        __syncthreads();
    }

    const int k = min(3 * g_num_pos[n], NP - 1);
    int running = csum[tid] - c;                        // count in bins beyond my chunk
    for (int j = 15; j >= 0; j--) {
        int E = running;                                // count of bins > (tid*16+j)
        running += (int)h[tid * 16 + j];
        if (E < k && running >= k) {                    // unique bin
            g_selB[n]  = tid * 16 + j;
            g_selkr[n] = k - E;
        }
    }
}

// ---------------- kernel E: gather — sum high bins, collect threshold bin ----------------
__global__ void k_gather() {     // grid (GSEG, NB) x 1024
    const int n   = blockIdx.y;
    const int tid = threadIdx.x;
    const int B   = g_selB[n];
    const int start = blockIdx.x * 4096;
    const int end   = min(start + 4096, NP);

    double local = 0.0;
    for (int i = start + tid; i < end; i += 1024) {
        float f = g_mined[(size_t)n * NP + i];
        unsigned b = __float_as_uint(f) >> 20;
        if ((int)b > B) local += (double)f;
        else if ((int)b == B) {
            int idx = atomicAdd(&g_cnt[n], 1);
            g_cand[(size_t)n * NP + idx] = f;
        }
    }
#pragma unroll
    for (int o = 16; o; o >>= 1)
        local += __shfl_down_sync(0xFFFFFFFFu, local, o);
    __shared__ double s_sum;
    if (tid == 0) s_sum = 0.0;
    __syncthreads();
    if ((tid & 31) == 0 && local != 0.0) atomicAdd(&s_sum, local);
    __syncthreads();
    if (tid == 0 && s_sum != 0.0) atomicAdd(&g_sumhi[n], s_sum);
}

// ---------------- kernel F: exact kr-th largest among candidates + final sum ----------------
__global__ void k_sel2() {       // 64 blocks x 256 threads
    const int n = blockIdx.x, tid = threadIdx.x;
    const int ncand = g_cnt[n];
    const int B = g_selB[n];
    int kr = g_selkr[n];

    __shared__ int hist[256];
    __shared__ unsigned s_pref; __shared__ int s_kr;

    unsigned prefix = (unsigned)B;            // top-12 bits established
    // radix over low 20 bits: widths 8, 8, 4
    const int shifts[3] = {12, 4, 0};
    const int widths[3] = {8, 8, 4};
    for (int pass = 0; pass < 3; pass++) {
        const int sh = shifts[pass], wd = widths[pass];
        const unsigned mask = (1u << wd) - 1u;
        if (tid < 256) hist[tid] = 0;
        __syncthreads();
        for (int i = tid; i < ncand; i += 256) {
            unsigned bits = __float_as_uint(g_cand[(size_t)n * NP + i]);
            if ((bits >> (sh + wd)) == prefix)
                atomicAdd(&hist[(bits >> sh) & mask], 1);
        }
        __syncthreads();
        if (tid == 0) {
            int acc = 0, d = (int)mask;
            for (; d > 0; d--) { if (acc + hist[d] >= kr) break; acc += hist[d]; }
            s_pref = (prefix << wd) | (unsigned)d;
            s_kr   = kr - acc;
        }
        __syncthreads();
        prefix = s_pref; kr = s_kr;
        __syncthreads();
    }

    const float u = __uint_as_float(prefix);
    float sum_gt = 0.0f;
    for (int i = tid; i < ncand; i += 256) {
        float f = g_cand[(size_t)n * NP + i];
        if (f > u) sum_gt += f;
    }
#pragma unroll
    for (int o = 16; o; o >>= 1)
        sum_gt += __shfl_down_sync(0xFFFFFFFFu, sum_gt, o);
    __shared__ float s_sg;
    if (tid == 0) s_sg = 0.0f;
    __syncthreads();
    if ((tid & 31) == 0 && sum_gt != 0.0f) atomicAdd(&s_sg, sum_gt);
    __syncthreads();
    if (tid == 0) {
        double S = g_sumhi[n] + (double)s_sg + (double)kr * (double)u;
        atomicAdd(&g_loss_c, S);
    }
}

// ---------------- kernel G: finalize ----------------
__global__ void k_final(float* out, int out_size) {
    if (threadIdx.x == 0 && blockIdx.x == 0) {
        int ntot = 0;
        for (int i = 0; i < NB; i++) ntot += g_num_pos[i];
        float nf = (float)ntot;
        out[0] = (float)(g_loss_l / (double)nf);
        if (out_size > 1) out[1] = (float)(g_loss_c / (double)nf);
    }
}

// ---------------- launch ----------------
extern "C" void kernel_launch(void* const* d_in, const int* in_sizes, int n_in,
                              void* d_out, int out_size) {
    const float* loc     = (const float*)d_in[0];
    const float* conf    = (const float*)d_in[1];
    const float* priors  = (const float*)d_in[2];
    const float* targets = (const float*)d_in[3];
    float* out = (float*)d_out;

    dim3 grid(NBLK, NB);
    k_init<<<(NB * NHB + 255) / 256, 256>>>();
    k_fused<<<grid, TPB>>>(loc, conf, priors, targets);
    k_force<<<2, 1024>>>(loc, conf, priors, targets);
    k_sel<<<NB, 256>>>();
    k_gather<<<dim3(GSEG, NB), 1024>>>();
    k_sel2<<<NB, 256>>>();
    k_final<<<1, 32>>>(out, out_size);
}